// round 15
// baseline (speedup 1.0000x reference)
#include <cuda_runtime.h>
#include <cuda_fp16.h>
#include <math.h>
#include <cstdint>

// Problem constants (fixed by reference setup_inputs)
#define Bb   32
#define Ss   512
#define Hh   512
#define Nn   (Bb*Ss)        // 16384 tokens
#define CN   4096           // 8 gates * H, interleaved c = k*8 + g
#define KXT  2560           // [h | hb | ha | sw_h | emb]
#define NLAYERS 4

// HMMA GEMM: 256x128 tile, 512 threads (16 warps, 8x2), BK=64
// big GEMM: A fp16 x B fp16 (1-term, 4 stages, fragment double-buffered).
// gf GEMM:  B split hi/lo (2-term, 3 stages, single-buffered).
#define BM 256
#define BN 128
#define BK 64
#define AROW 72                        // BK + 8 pad (halves); 144 bytes/row
#define A_BYTES  (BM*AROW*2)           // 36864
#define B_BYTES  (BN*AROW*2)           // 18432 per plane
#define SMEM_BYTES 221184              // = 4*(A+B) = 3*(A+2B); zs 256*132*4=135168 fits

// ---------------- device scratch ----------------
__device__ __half g_XA [(size_t)Nn*KXT];   // A single fp16
__device__ __half g_WH [(size_t)CN*KXT];   // W fp16 [c][j]
__device__ __half g_GH [(size_t)Hh*Hh];    // gWhf hi [c][j]
__device__ __half g_GL [(size_t)Hh*Hh];    // gWhf lo
__device__ __half g_hA [(size_t)Nn*Hh];    // h fp16 (gf GEMM A)
__device__ float g_h  [(size_t)Nn*Hh];
__device__ float g_c  [(size_t)Nn*Hh];
__device__ float g_cb [(size_t)Nn*Hh];
__device__ float g_ca [(size_t)Nn*Hh];
__device__ float g_swc[(size_t)Nn*Hh];
__device__ float g_gf [(size_t)Nn*Hh];
__device__ float g_zd [Bb*CN];
__device__ float g_dh [2][Bb*Hh];
__device__ float g_dc [2][Bb*Hh];
__device__ float g_comb[Bb*Hh];
__device__ float g_gd [Bb*Hh];
__device__ float g_go [Bb*Hh];
__device__ float g_gfx[Bb*Hh];

__device__ __forceinline__ float sigm(float x) { return 1.f/(1.f+__expf(-x)); }
__device__ __forceinline__ void split2h(float v, __half& hi, __half& lo) {
    hi = __float2half_rn(v);
    lo = __float2half_rn(v - __half2float(hi));
}

__device__ __forceinline__ uint32_t smem_u32(const void* p) {
    uint32_t a;
    asm("{ .reg .u64 t; cvta.to.shared.u64 t, %1; cvt.u32.u64 %0, t; }" : "=r"(a) : "l"(p));
    return a;
}
__device__ __forceinline__ void mma16816(float* c, const uint32_t* a, uint32_t b0, uint32_t b1) {
    asm volatile("mma.sync.aligned.m16n8k16.row.col.f32.f16.f16.f32 "
        "{%0,%1,%2,%3},{%4,%5,%6,%7},{%8,%9},{%0,%1,%2,%3};"
        : "+f"(c[0]), "+f"(c[1]), "+f"(c[2]), "+f"(c[3])
        : "r"(a[0]), "r"(a[1]), "r"(a[2]), "r"(a[3]), "r"(b0), "r"(b1));
}
#define LDSM_X4(r, addr) \
    asm volatile("ldmatrix.sync.aligned.m8n8.x4.shared.b16 {%0,%1,%2,%3},[%4];" \
        : "=r"((r)[0]), "=r"((r)[1]), "=r"((r)[2]), "=r"((r)[3]) : "r"(addr))
#define CP_ASYNC(dst, src) \
    asm volatile("cp.async.cg.shared.global [%0],[%1],16;" :: "r"(dst), "l"(src))
#define CP_COMMIT() asm volatile("cp.async.commit_group;")

// ---------------- HMMA mainloop: C[256x128], BK=64, templated B-split ----------------
template<int KCHUNKS, int NST, bool SPLITB>
__device__ __forceinline__ void hmma_mainloop(
    const __half* __restrict__ AAp, int lda,
    const __half* __restrict__ BHp, const __half* __restrict__ BLp, int ldb,
    int n0, int c0, char* smem, float acc[2][8][4])
{
    constexpr int STG = A_BYTES + (SPLITB ? 2 : 1)*B_BYTES;
    constexpr uint32_t BH_OFF = A_BYTES;
    constexpr uint32_t BL_OFF = A_BYTES + B_BYTES;
    const int tid = threadIdx.x, lane = tid & 31, wid = tid >> 5;
    const int wm = wid >> 1, wn = wid & 1;          // 8x2 warps, warp tile 32x64
    const uint32_t sb = smem_u32(smem);

    const uint32_t a_off0 = (uint32_t)(((wm*32 + (lane & 15))*AROW + (lane >> 4)*8) * 2);
    const uint32_t a_off1 = a_off0 + 16*AROW*2;
    const uint32_t b_off  = (uint32_t)(((wn*64 + ((lane >> 4) << 3) + (lane & 7))*AROW
                                        + ((lane >> 3) & 1)*8) * 2);

    auto issue = [&](int t) {
        const uint32_t base = sb + (t % NST)*STG;
        #pragma unroll
        for (int i = 0; i < 4; i++) {               // A: 2048 segs
            const int q = tid + i*512;
            const int row = q >> 3, seg = q & 7;
            const uint32_t off = (uint32_t)((row*AROW + seg*8)*2);
            CP_ASYNC(base + off, AAp + (size_t)(n0+row)*lda + t*BK + seg*8);
        }
        #pragma unroll
        for (int i = 0; i < 2; i++) {               // B: 1024 segs per plane
            const int q = tid + i*512;
            const int row = q >> 3, seg = q & 7;
            const uint32_t off = (uint32_t)((row*AROW + seg*8)*2);
            const size_t gsrcB = (size_t)(c0+row)*ldb + t*BK + seg*8;
            CP_ASYNC(base + BH_OFF + off, BHp + gsrcB);
            if (SPLITB) CP_ASYNC(base + BL_OFF + off, BLp + gsrcB);
        }
        CP_COMMIT();
    };

    #pragma unroll
    for (int i = 0; i < NST-1; i++) issue(i);
    #pragma unroll 1
    for (int t = 0; t < KCHUNKS; t++) {
        if (NST >= 4 && t + 3 <= KCHUNKS) asm volatile("cp.async.wait_group 2;");
        else if (t + 2 <= KCHUNKS)        asm volatile("cp.async.wait_group 1;");
        else                              asm volatile("cp.async.wait_group 0;");
        __syncthreads();
        if (t + NST - 1 < KCHUNKS) issue(t + NST - 1);   // stage (t-1)%NST: safe post-barrier
        const uint32_t base = sb + (t % NST)*STG;
        if (!SPLITB) {
            // fragment double-buffered path: LDSM for step st+1 in flight
            // while MMAs of step st execute (st = ks*4 + bp, 16 steps).
            uint32_t Ar[2][2][4];   // [parity(ks)][am][4]
            uint32_t Br[2][4];      // [parity(st)][4]
            LDSM_X4(Ar[0][0], base + a_off0);
            LDSM_X4(Ar[0][1], base + a_off1);
            LDSM_X4(Br[0],    base + BH_OFF + b_off);
            #pragma unroll
            for (int ks = 0; ks < 4; ks++) {
                const int kp = ks & 1;
                if (ks < 3) {
                    LDSM_X4(Ar[kp^1][0], base + a_off0 + (ks+1)*32);
                    LDSM_X4(Ar[kp^1][1], base + a_off1 + (ks+1)*32);
                }
                #pragma unroll
                for (int bp = 0; bp < 4; bp++) {
                    const int st = ks*4 + bp;
                    const int p = st & 1;
                    if (st < 15) {
                        const int nst = st + 1;
                        const int nks = nst >> 2, nbp = nst & 3;
                        LDSM_X4(Br[p^1], base + BH_OFF + b_off + nbp*16*AROW*2 + nks*32);
                    }
                    mma16816(acc[0][2*bp],   Ar[kp][0], Br[p][0], Br[p][1]);
                    mma16816(acc[0][2*bp+1], Ar[kp][0], Br[p][2], Br[p][3]);
                    mma16816(acc[1][2*bp],   Ar[kp][1], Br[p][0], Br[p][1]);
                    mma16816(acc[1][2*bp+1], Ar[kp][1], Br[p][2], Br[p][3]);
                }
            }
        } else {
            #pragma unroll
            for (int ks = 0; ks < 4; ks++) {
                const uint32_t kb = (uint32_t)(ks*32);  // 16 halves per k-step
                uint32_t Ahf[2][4];
                LDSM_X4(Ahf[0], base + a_off0 + kb);
                LDSM_X4(Ahf[1], base + a_off1 + kb);
                #pragma unroll
                for (int bp = 0; bp < 4; bp++) {
                    uint32_t Bhf[4], Blf[4];
                    LDSM_X4(Bhf, base + BH_OFF + b_off + bp*16*AROW*2 + kb);
                    LDSM_X4(Blf, base + BL_OFF + b_off + bp*16*AROW*2 + kb);
                    #pragma unroll
                    for (int am = 0; am < 2; am++) {
                        mma16816(acc[am][2*bp],   Ahf[am], Bhf[0], Bhf[1]);
                        mma16816(acc[am][2*bp+1], Ahf[am], Bhf[2], Bhf[3]);
                        mma16816(acc[am][2*bp],   Ahf[am], Blf[0], Blf[1]);
                        mma16816(acc[am][2*bp+1], Ahf[am], Blf[2], Blf[3]);
                    }
                }
            }
        }
    }
}

// ---------------- big GEMM + fused SLSTM epilogue ----------------
__global__ void __launch_bounds__(512) k_hgemm_big(
    const float* __restrict__ bias, const int* __restrict__ mask,
    float* __restrict__ out, int cur, int last)
{
    extern __shared__ char smem[];
    const int n0 = blockIdx.y*BM, c0 = blockIdx.x*BN;
    float acc[2][8][4] = {};
    hmma_mainloop<KXT/BK, 4, false>(g_XA, KXT, g_WH, nullptr, KXT, n0, c0, smem, acc);

    // stage z to smem (row stride 132 floats, 256 rows)
    float* zs = (float*)smem;
    const int lane = threadIdx.x & 31, wid = threadIdx.x >> 5;
    const int wm = wid >> 1, wn = wid & 1;
    const int g = lane >> 2, tg2 = (lane & 3)*2;
    __syncthreads();
    #pragma unroll
    for (int am = 0; am < 2; am++) {
        const int ra = wm*32 + am*16 + g;
        #pragma unroll
        for (int na = 0; na < 8; na++) {
            const int col = wn*64 + na*8 + tg2;
            *(float2*)&zs[ra*132 + col]     = *(float2*)&acc[am][na][0];
            *(float2*)&zs[(ra+8)*132 + col] = *(float2*)&acc[am][na][2];
        }
    }
    __syncthreads();

    // per-unit epilogue: 16 units x 256 rows in this tile
    const int u = threadIdx.x & 15, rgrp = threadIdx.x >> 4;   // 32 rgrps x 8 rows
    const int kout = (c0 >> 3) + u;
    const float* dc_old = g_dc[cur];
    float* hout = last ? out : g_h;
    float bz[8];
    #pragma unroll
    for (int gg = 0; gg < 8; gg++) bz[gg] = bias[gg*512 + kout];

    #pragma unroll 1
    for (int i = 0; i < 8; i++) {
        const int n = n0 + rgrp*8 + i;
        const int b = n >> 9;
        const float m = (float)mask[n];
        float z[8];
        *(float4*)&z[0] = *(float4*)&zs[(rgrp*8+i)*132 + u*8];
        *(float4*)&z[4] = *(float4*)&zs[(rgrp*8+i)*132 + u*8 + 4];
        #pragma unroll
        for (int gg = 0; gg < 8; gg++)
            z[gg] += g_zd[(b<<12)+(kout<<3)+gg] + bz[gg];
        float e[6], ssum = 0.f;
        #pragma unroll
        for (int j = 0; j < 6; j++) { e[j] = __expf(sigm(z[j])); ssum += e[j]; }
        const float inv = 1.f/ssum;
        const float o = sigm(z[6]);
        const float u_t = tanhf(z[7]);
        const size_t idx = ((size_t)n << 9) + kout;
        float cn = (e[0]*g_cb[idx] + e[1]*g_ca[idx] + e[2]*g_c[idx]
                  + e[3]*dc_old[(b<<9)+kout] + e[4]*g_swc[idx] + e[5]*u_t) * inv;
        cn *= m;
        const float hv = o * tanhf(cn) * m;
        hout[idx] = hv;
        g_c[idx]  = cn;
        g_hA[idx] = __float2half_rn(hv);
    }
}

// ---------------- gf GEMM: gf = sigmoid(h @ gWhf + gfx + gbf) + mask_score ----------------
__global__ void __launch_bounds__(512) k_hgemm_gf(
    const float* __restrict__ gbf, const int* __restrict__ mask)
{
    extern __shared__ char smem[];
    const int n0 = blockIdx.y*BM, c0 = blockIdx.x*BN;
    float acc[2][8][4] = {};
    hmma_mainloop<Hh/BK, 3, true>(g_hA, Hh, g_GH, g_GL, Hh, n0, c0, smem, acc);

    const int lane = threadIdx.x & 31, wid = threadIdx.x >> 5;
    const int wm = wid >> 1, wn = wid & 1;
    const int g = lane >> 2, tg2 = (lane & 3)*2;
    #pragma unroll
    for (int am = 0; am < 2; am++) {
        #pragma unroll
        for (int half = 0; half < 2; half++) {
            const int n = n0 + wm*32 + am*16 + g + half*8;
            const int b = n >> 9;
            const float ms = mask[n] ? 0.f : -1e25f;
            #pragma unroll
            for (int na = 0; na < 8; na++) {
                const int cc = c0 + wn*64 + na*8 + tg2;
                float2 r;
                r.x = sigm(acc[am][na][half*2+0] + g_gfx[(b<<9)+cc]   + gbf[cc])   + ms;
                r.y = sigm(acc[am][na][half*2+1] + g_gfx[(b<<9)+cc+1] + gbf[cc+1]) + ms;
                *(float2*)&g_gf[((size_t)n<<9) + cc] = r;
            }
        }
    }
}

// ---------------- one-time prep (weights) + init (inputs), merged ----------------
#define PREP_ELEMS ((size_t)CN*KXT + (size_t)Hh*Hh)
#define PREP_BLOCKS ((int)(PREP_ELEMS/256))          // 41984
#define INIT_BLOCKS ((Nn*Hh)/256)                    // 32768
__global__ void k_prep_init(
    const float* __restrict__ Wx, const float* __restrict__ Wh,
    const float* __restrict__ Wi, const float* __restrict__ Ws,
    const float* __restrict__ gWhf,
    const float* __restrict__ word, const float* __restrict__ ih,
    const float* __restrict__ icc, const int* __restrict__ mask)
{
    if (blockIdx.x < PREP_BLOCKS) {
        size_t idx = (size_t)blockIdx.x*256 + threadIdx.x;
        if (idx < (size_t)CN*KXT) {
            int c = (int)(idx / KXT), j = (int)(idx % KXT);
            int g = c & 7, k = c >> 3;
            float v;
            if (j < 512)        v = Wx[((size_t)((g<<9)  + j       ))*512 + k];
            else if (j < 1536)  v = Wh[((size_t)((g<<10) + (j-512) ))*512 + k];
            else if (j < 2048)  v = Ws[((size_t)((g<<9)  + (j-1536)))*512 + k];
            else                v = Wi[((size_t)((g<<9)  + (j-2048)))*512 + k];
            g_WH[idx] = __float2half_rn(v);
        } else {
            int r = (int)(idx - (size_t)CN*KXT);     // < 512*512
            int kcol = r >> 9, j = r & 511;
            split2h(gWhf[j*512 + kcol], g_GH[r], g_GL[r]);
        }
    } else {
        size_t idx = (size_t)(blockIdx.x - PREP_BLOCKS)*256 + threadIdx.x;  // < Nn*512
        int n = (int)(idx >> 9), k = (int)(idx & 511);
        float m = (float)mask[n];
        float hv = ih[idx]*m;
        g_h[idx]  = hv;
        g_hA[idx] = __float2half_rn(hv);
        g_c[idx]  = icc[idx]*m;
        g_XA[(size_t)n*KXT + 2048 + k] = __float2half_rn(word[idx]*m);
    }
}

// mean(h)->dh[0] (y=0) and mean(c)->dc[0] (y=1), 4-way unrolled for MLP
__global__ void k_meanhc() {
    int b = blockIdx.x, k = threadIdx.x;
    const float* x = (blockIdx.y ? g_c : g_h) + ((size_t)(b<<9))*512 + k;
    float s0=0.f, s1=0.f, s2=0.f, s3=0.f;
    for (int t = 0; t < Ss; t += 4) {
        s0 += x[(size_t)t*512];       s1 += x[(size_t)(t+1)*512];
        s2 += x[(size_t)(t+2)*512];   s3 += x[(size_t)(t+3)*512];
    }
    float s = ((s0+s1)+(s2+s3)) * (1.f/512.f);
    int o = (b<<9) + k;
    if (blockIdx.y) g_dc[0][o] = s; else g_dh[0][o] = s;
}

// mean(h)->comb (layers >= 1)
__global__ void k_mean0() {
    int b = blockIdx.x, k = threadIdx.x;
    const float* x = g_h + ((size_t)(b<<9))*512 + k;
    float s0=0.f, s1=0.f, s2=0.f, s3=0.f;
    for (int t = 0; t < Ss; t += 4) {
        s0 += x[(size_t)t*512];       s1 += x[(size_t)(t+1)*512];
        s2 += x[(size_t)(t+2)*512];   s3 += x[(size_t)(t+3)*512];
    }
    g_comb[(b<<9) + k] = ((s0+s1)+(s2+s3)) * (1.f/512.f);
}

// small per-batch GEMMs: gd, go, gfx, zd[g]. layer0: comb == dh[0]
__global__ void k_small(const float* __restrict__ gW, const float* __restrict__ gb,
                        const float* __restrict__ Wd, int cur, int layer0) {
    int t = blockIdx.y;
    int idx = blockIdx.x*256 + threadIdx.x;   // 0..16383 = (b,k)
    int b = idx >> 9, k = idx & 511;
    const float* dh = g_dh[cur] + (b<<9);
    float s = 0.f;
    if (t <= 1) {
        const float* W1 = gW + (size_t)(t*2  )*262144;
        const float* W2 = gW + (size_t)(t*2+1)*262144;
        const float* cm = (layer0 ? g_dh[cur] : g_comb) + (b<<9);
        for (int j = 0; j < 512; j++)
            s = fmaf(dh[j], W1[j*512+k], fmaf(cm[j], W2[j*512+k], s));
        float v = sigm(s + gb[t*512 + k]);
        if (t == 0) g_gd[idx] = v; else g_go[idx] = v;
    } else if (t == 2) {
        const float* W = gW + (size_t)4*262144;   // gWxf
        for (int j = 0; j < 512; j++) s = fmaf(dh[j], W[j*512+k], s);
        g_gfx[idx] = s;
    } else {
        int g = t - 3;
        const float* W = Wd + (size_t)g*262144;
        for (int j = 0; j < 512; j++) s = fmaf(dh[j], W[j*512+k], s);
        g_zd[(b<<12) + (k<<3) + g] = s;
    }
}

// softmax over S+1 entries per (b,k) + new dummies
__global__ void k_soft(int cur) {
    int b = blockIdx.x, k = threadIdx.x;
    int bk = (b<<9) + k;
    float den = __expf(g_gd[bk] - 1.f);
    float num = den * g_dc[cur][bk];
    const float* gf = g_gf + (size_t)b*Ss*Hh + k;
    const float* cp = g_c  + (size_t)b*Ss*Hh + k;
    for (int s = 0; s < Ss; s++) {
        float w = __expf(gf[s*512] - 1.f);
        num = fmaf(w, cp[s*512], num);
        den += w;
    }
    float dcn = num/den;
    g_dc[cur^1][bk] = dcn;
    g_dh[cur^1][bk] = g_go[bk]*tanhf(dcn);
}

// X cols 0..2047 = [h | hb | ha | sw_h] fp16; also cb, ca, swc (fp32)
__global__ void k_build(const int* __restrict__ pos) {
    int n = blockIdx.x, k = threadIdx.x;
    int b = n >> 9, s = n & 511;
    size_t base = ((size_t)n << 9) + k;
    float hv = g_h[base];
    float hb = (s >= 1 ? g_h[base-512] : 0.f) + (s >= 2 ? g_h[base-1024] : 0.f);
    float ha = (s <= 510 ? g_h[base+512] : 0.f) + (s <= 509 ? g_h[base+1024] : 0.f);
    int p = pos[n];
    float sh = 0.f, sc = 0.f;
    if (p > 0) {
        size_t pb = ((size_t)((b<<9) + p - 1) << 9) + k;
        sh = g_h[pb]; sc = g_c[pb];
    }
    size_t xb = (size_t)n*KXT + k;
    g_XA[xb]        = __float2half_rn(hv);
    g_XA[xb + 512]  = __float2half_rn(hb);
    g_XA[xb + 1024] = __float2half_rn(ha);
    g_XA[xb + 1536] = __float2half_rn(sh);
    g_cb[base]  = (s >= 1 ? g_c[base-512] : 0.f) + (s >= 2 ? g_c[base-1024] : 0.f);
    g_ca[base]  = (s <= 510 ? g_c[base+512] : 0.f) + (s <= 509 ? g_c[base+1024] : 0.f);
    g_swc[base] = sc;
}

// ---------------- host ----------------
extern "C" void kernel_launch(void* const* d_in, const int* in_sizes, int n_in,
                              void* d_out, int out_size) {
    const float* word = (const float*)d_in[0];
    const float* ih   = (const float*)d_in[1];
    const float* icc  = (const float*)d_in[2];
    const float* Wx   = (const float*)d_in[3];
    const float* Wh   = (const float*)d_in[4];
    const float* Wi   = (const float*)d_in[5];
    const float* Wd   = (const float*)d_in[6];
    const float* Ws   = (const float*)d_in[7];
    const float* bias = (const float*)d_in[8];
    const float* gW   = (const float*)d_in[9];
    const float* gb   = (const float*)d_in[10];
    const int*   pos  = (const int*)d_in[11];
    const int*   mask = (const int*)d_in[12];
    float* out = (float*)d_out;

    cudaFuncSetAttribute(k_hgemm_big, cudaFuncAttributeMaxDynamicSharedMemorySize, SMEM_BYTES);
    cudaFuncSetAttribute(k_hgemm_gf,  cudaFuncAttributeMaxDynamicSharedMemorySize, SMEM_BYTES);

    k_prep_init<<<PREP_BLOCKS + INIT_BLOCKS, 256>>>(
        Wx, Wh, Wi, Ws, gW + (size_t)5*262144, word, ih, icc, mask);
    k_meanhc<<<dim3(Bb, 2), 512>>>();

    dim3 gbig(CN/BN, Nn/BM);   // (32, 64)
    dim3 ggf (Hh/BN, Nn/BM);   // (4, 64)
    int cur = 0;
    for (int layer = 0; layer < NLAYERS; layer++) {
        if (layer > 0) k_mean0<<<Bb, 512>>>();
        k_small<<<dim3(64, 11), 256>>>(gW, gb, Wd, cur, layer == 0);
        k_hgemm_gf<<<ggf, 512, SMEM_BYTES>>>(gb + 1024, mask);
        k_soft <<<Bb, 512>>>(cur);
        k_build<<<Nn, 512>>>(pos);
        k_hgemm_big<<<gbig, 512, SMEM_BYTES>>>(bias, mask, out, cur, layer == NLAYERS-1);
        cur ^= 1;
    }
}

// round 16
// speedup vs baseline: 1.0699x; 1.0699x over previous
#include <cuda_runtime.h>
#include <cuda_fp16.h>
#include <math.h>
#include <cstdint>

// Problem constants (fixed by reference setup_inputs)
#define Bb   32
#define Ss   512
#define Hh   512
#define Nn   (Bb*Ss)        // 16384 tokens
#define CN   4096           // 8 gates * H, interleaved c = k*8 + g
#define KXT  2560           // XA cols: [h | hb | ha | sw_h | emb]
#define KLY  2048           // per-layer GEMM K (emb hoisted into Zc)
#define NLAYERS 4

// HMMA GEMM: 256x128 tile, 512 threads (16 warps, 8x2), BK=64
#define BM 256
#define BN 128
#define BK 64
#define AROW 72                        // BK + 8 pad (halves); 144 bytes/row
#define A_BYTES  (BM*AROW*2)           // 36864
#define B_BYTES  (BN*AROW*2)           // 18432 per plane
#define SMEM_BYTES 221184              // = 4*(A+B) = 3*(A+2B); zs 256*132*4=135168 fits

// ---------------- device scratch ----------------
__device__ __half g_XA [(size_t)Nn*KXT];   // A single fp16 (cols 2048.. = emb)
__device__ __half g_WH [(size_t)CN*KXT];   // W fp16 [c][j] (cols 2048.. = Wi)
__device__ __half g_GH [(size_t)Hh*Hh];    // gWhf hi [c][j]
__device__ __half g_GL [(size_t)Hh*Hh];    // gWhf lo
__device__ __half g_hA [(size_t)Nn*Hh];    // h fp16 (gf GEMM A)
__device__ float g_Zc [(size_t)Nn*CN];     // emb@Wi + bias (layer-invariant), fp32
__device__ float g_h  [(size_t)Nn*Hh];
__device__ float g_c  [(size_t)Nn*Hh];
__device__ float g_cb [(size_t)Nn*Hh];
__device__ float g_ca [(size_t)Nn*Hh];
__device__ float g_swc[(size_t)Nn*Hh];
__device__ float g_gf [(size_t)Nn*Hh];
__device__ float g_zd [Bb*CN];
__device__ float g_dh [2][Bb*Hh];
__device__ float g_dc [2][Bb*Hh];
__device__ float g_comb[Bb*Hh];
__device__ float g_gd [Bb*Hh];
__device__ float g_go [Bb*Hh];
__device__ float g_gfx[Bb*Hh];

__device__ __forceinline__ float sigm(float x) { return 1.f/(1.f+__expf(-x)); }
__device__ __forceinline__ void split2h(float v, __half& hi, __half& lo) {
    hi = __float2half_rn(v);
    lo = __float2half_rn(v - __half2float(hi));
}

__device__ __forceinline__ uint32_t smem_u32(const void* p) {
    uint32_t a;
    asm("{ .reg .u64 t; cvta.to.shared.u64 t, %1; cvt.u32.u64 %0, t; }" : "=r"(a) : "l"(p));
    return a;
}
__device__ __forceinline__ void mma16816(float* c, const uint32_t* a, uint32_t b0, uint32_t b1) {
    asm volatile("mma.sync.aligned.m16n8k16.row.col.f32.f16.f16.f32 "
        "{%0,%1,%2,%3},{%4,%5,%6,%7},{%8,%9},{%0,%1,%2,%3};"
        : "+f"(c[0]), "+f"(c[1]), "+f"(c[2]), "+f"(c[3])
        : "r"(a[0]), "r"(a[1]), "r"(a[2]), "r"(a[3]), "r"(b0), "r"(b1));
}
#define LDSM_X4(r, addr) \
    asm volatile("ldmatrix.sync.aligned.m8n8.x4.shared.b16 {%0,%1,%2,%3},[%4];" \
        : "=r"((r)[0]), "=r"((r)[1]), "=r"((r)[2]), "=r"((r)[3]) : "r"(addr))
#define CP_ASYNC(dst, src) \
    asm volatile("cp.async.cg.shared.global [%0],[%1],16;" :: "r"(dst), "l"(src))
#define CP_COMMIT() asm volatile("cp.async.commit_group;")

// ---------------- HMMA mainloop: C[256x128], BK=64, templated B-split ----------------
template<int KCHUNKS, int NST, bool SPLITB>
__device__ __forceinline__ void hmma_mainloop(
    const __half* __restrict__ AAp, int lda,
    const __half* __restrict__ BHp, const __half* __restrict__ BLp, int ldb,
    int n0, int c0, char* smem, float acc[2][8][4])
{
    constexpr int STG = A_BYTES + (SPLITB ? 2 : 1)*B_BYTES;
    constexpr uint32_t BH_OFF = A_BYTES;
    constexpr uint32_t BL_OFF = A_BYTES + B_BYTES;
    const int tid = threadIdx.x, lane = tid & 31, wid = tid >> 5;
    const int wm = wid >> 1, wn = wid & 1;          // 8x2 warps, warp tile 32x64
    const uint32_t sb = smem_u32(smem);

    const uint32_t a_off0 = (uint32_t)(((wm*32 + (lane & 15))*AROW + (lane >> 4)*8) * 2);
    const uint32_t a_off1 = a_off0 + 16*AROW*2;
    const uint32_t b_off  = (uint32_t)(((wn*64 + ((lane >> 4) << 3) + (lane & 7))*AROW
                                        + ((lane >> 3) & 1)*8) * 2);

    auto issue = [&](int t) {
        const uint32_t base = sb + (t % NST)*STG;
        #pragma unroll
        for (int i = 0; i < 4; i++) {               // A: 2048 segs
            const int q = tid + i*512;
            const int row = q >> 3, seg = q & 7;
            const uint32_t off = (uint32_t)((row*AROW + seg*8)*2);
            CP_ASYNC(base + off, AAp + (size_t)(n0+row)*lda + t*BK + seg*8);
        }
        #pragma unroll
        for (int i = 0; i < 2; i++) {               // B: 1024 segs per plane
            const int q = tid + i*512;
            const int row = q >> 3, seg = q & 7;
            const uint32_t off = (uint32_t)((row*AROW + seg*8)*2);
            const size_t gsrcB = (size_t)(c0+row)*ldb + t*BK + seg*8;
            CP_ASYNC(base + BH_OFF + off, BHp + gsrcB);
            if (SPLITB) CP_ASYNC(base + BL_OFF + off, BLp + gsrcB);
        }
        CP_COMMIT();
    };

    #pragma unroll
    for (int i = 0; i < NST-1; i++) issue(i);
    #pragma unroll 1
    for (int t = 0; t < KCHUNKS; t++) {
        if (NST >= 4 && t + 3 <= KCHUNKS) asm volatile("cp.async.wait_group 2;");
        else if (t + 2 <= KCHUNKS)        asm volatile("cp.async.wait_group 1;");
        else                              asm volatile("cp.async.wait_group 0;");
        __syncthreads();
        if (t + NST - 1 < KCHUNKS) issue(t + NST - 1);   // stage (t-1)%NST: safe post-barrier
        const uint32_t base = sb + (t % NST)*STG;
        #pragma unroll
        for (int ks = 0; ks < 4; ks++) {
            const uint32_t kb = (uint32_t)(ks*32);  // 16 halves per k-step
            uint32_t Ahf[2][4];
            LDSM_X4(Ahf[0], base + a_off0 + kb);
            LDSM_X4(Ahf[1], base + a_off1 + kb);
            #pragma unroll
            for (int bp = 0; bp < 4; bp++) {
                uint32_t Bhf[4];
                LDSM_X4(Bhf, base + BH_OFF + b_off + bp*16*AROW*2 + kb);
                #pragma unroll
                for (int am = 0; am < 2; am++) {
                    mma16816(acc[am][2*bp],   Ahf[am], Bhf[0], Bhf[1]);
                    mma16816(acc[am][2*bp+1], Ahf[am], Bhf[2], Bhf[3]);
                }
                if (SPLITB) {
                    uint32_t Blf[4];
                    LDSM_X4(Blf, base + BL_OFF + b_off + bp*16*AROW*2 + kb);
                    #pragma unroll
                    for (int am = 0; am < 2; am++) {
                        mma16816(acc[am][2*bp],   Ahf[am], Blf[0], Blf[1]);
                        mma16816(acc[am][2*bp+1], Ahf[am], Blf[2], Blf[3]);
                    }
                }
            }
        }
    }
}

// ---------------- one-time Zc GEMM: Zc = emb @ Wi + bias (K=512) ----------------
__global__ void __launch_bounds__(512) k_hgemm_zc(const float* __restrict__ bias) {
    extern __shared__ char smem[];
    const int n0 = blockIdx.y*BM, c0 = blockIdx.x*BN;
    float acc[2][8][4] = {};
    hmma_mainloop<512/BK, 4, false>(g_XA + 2048, KXT, g_WH + 2048, nullptr, KXT,
                                    n0, c0, smem, acc);
    const int lane = threadIdx.x & 31, wid = threadIdx.x >> 5;
    const int wm = wid >> 1, wn = wid & 1;
    const int g = lane >> 2, tg2 = (lane & 3)*2;
    #pragma unroll
    for (int am = 0; am < 2; am++) {
        #pragma unroll
        for (int half = 0; half < 2; half++) {
            const int n = n0 + wm*32 + am*16 + g + half*8;
            #pragma unroll
            for (int na = 0; na < 8; na++) {
                const int cc = c0 + wn*64 + na*8 + tg2;
                float2 r;
                r.x = acc[am][na][half*2+0] + bias[(cc & 7)*512 + (cc >> 3)];
                r.y = acc[am][na][half*2+1] + bias[((cc+1) & 7)*512 + ((cc+1) >> 3)];
                *(float2*)&g_Zc[(size_t)n*CN + cc] = r;
            }
        }
    }
}

// ---------------- big GEMM (K=2048) + fused SLSTM epilogue ----------------
__global__ void __launch_bounds__(512) k_hgemm_big(
    const int* __restrict__ mask, float* __restrict__ out, int cur, int last)
{
    extern __shared__ char smem[];
    const int n0 = blockIdx.y*BM, c0 = blockIdx.x*BN;
    float acc[2][8][4] = {};
    hmma_mainloop<KLY/BK, 4, false>(g_XA, KXT, g_WH, nullptr, KXT, n0, c0, smem, acc);

    // stage z to smem (row stride 132 floats, 256 rows)
    float* zs = (float*)smem;
    const int lane = threadIdx.x & 31, wid = threadIdx.x >> 5;
    const int wm = wid >> 1, wn = wid & 1;
    const int g = lane >> 2, tg2 = (lane & 3)*2;
    __syncthreads();
    #pragma unroll
    for (int am = 0; am < 2; am++) {
        const int ra = wm*32 + am*16 + g;
        #pragma unroll
        for (int na = 0; na < 8; na++) {
            const int col = wn*64 + na*8 + tg2;
            *(float2*)&zs[ra*132 + col]     = *(float2*)&acc[am][na][0];
            *(float2*)&zs[(ra+8)*132 + col] = *(float2*)&acc[am][na][2];
        }
    }
    __syncthreads();

    // per-unit epilogue: 16 units x 256 rows in this tile
    const int u = threadIdx.x & 15, rgrp = threadIdx.x >> 4;   // 32 rgrps x 8 rows
    const int kout = (c0 >> 3) + u;
    const float* dc_old = g_dc[cur];
    float* hout = last ? out : g_h;

    #pragma unroll 1
    for (int i = 0; i < 8; i++) {
        const int n = n0 + rgrp*8 + i;
        const int b = n >> 9;
        const float m = (float)mask[n];
        float z[8];
        *(float4*)&z[0] = *(float4*)&zs[(rgrp*8+i)*132 + u*8];
        *(float4*)&z[4] = *(float4*)&zs[(rgrp*8+i)*132 + u*8 + 4];
        const float* zc = g_Zc + (size_t)n*CN + (kout<<3);
        float4 zc0 = *(const float4*)zc;
        float4 zc1 = *(const float4*)(zc + 4);
        z[0] += zc0.x; z[1] += zc0.y; z[2] += zc0.z; z[3] += zc0.w;
        z[4] += zc1.x; z[5] += zc1.y; z[6] += zc1.z; z[7] += zc1.w;
        #pragma unroll
        for (int gg = 0; gg < 8; gg++)
            z[gg] += g_zd[(b<<12)+(kout<<3)+gg];
        float e[6], ssum = 0.f;
        #pragma unroll
        for (int j = 0; j < 6; j++) { e[j] = __expf(sigm(z[j])); ssum += e[j]; }
        const float inv = 1.f/ssum;
        const float o = sigm(z[6]);
        const float u_t = tanhf(z[7]);
        const size_t idx = ((size_t)n << 9) + kout;
        float cn = (e[0]*g_cb[idx] + e[1]*g_ca[idx] + e[2]*g_c[idx]
                  + e[3]*dc_old[(b<<9)+kout] + e[4]*g_swc[idx] + e[5]*u_t) * inv;
        cn *= m;
        const float hv = o * tanhf(cn) * m;
        hout[idx] = hv;
        g_c[idx]  = cn;
        g_hA[idx] = __float2half_rn(hv);
    }
}

// ---------------- gf GEMM: gf = sigmoid(h @ gWhf + gfx + gbf) + mask_score ----------------
__global__ void __launch_bounds__(512) k_hgemm_gf(
    const float* __restrict__ gbf, const int* __restrict__ mask)
{
    extern __shared__ char smem[];
    const int n0 = blockIdx.y*BM, c0 = blockIdx.x*BN;
    float acc[2][8][4] = {};
    hmma_mainloop<Hh/BK, 3, true>(g_hA, Hh, g_GH, g_GL, Hh, n0, c0, smem, acc);

    const int lane = threadIdx.x & 31, wid = threadIdx.x >> 5;
    const int wm = wid >> 1, wn = wid & 1;
    const int g = lane >> 2, tg2 = (lane & 3)*2;
    #pragma unroll
    for (int am = 0; am < 2; am++) {
        #pragma unroll
        for (int half = 0; half < 2; half++) {
            const int n = n0 + wm*32 + am*16 + g + half*8;
            const int b = n >> 9;
            const float ms = mask[n] ? 0.f : -1e25f;
            #pragma unroll
            for (int na = 0; na < 8; na++) {
                const int cc = c0 + wn*64 + na*8 + tg2;
                float2 r;
                r.x = sigm(acc[am][na][half*2+0] + g_gfx[(b<<9)+cc]   + gbf[cc])   + ms;
                r.y = sigm(acc[am][na][half*2+1] + g_gfx[(b<<9)+cc+1] + gbf[cc+1]) + ms;
                *(float2*)&g_gf[((size_t)n<<9) + cc] = r;
            }
        }
    }
}

// ---------------- one-time prep (weights) + init (inputs), merged ----------------
#define PREP_ELEMS ((size_t)CN*KXT + (size_t)Hh*Hh)
#define PREP_BLOCKS ((int)(PREP_ELEMS/256))          // 41984
#define INIT_BLOCKS ((Nn*Hh)/256)                    // 32768
__global__ void k_prep_init(
    const float* __restrict__ Wx, const float* __restrict__ Wh,
    const float* __restrict__ Wi, const float* __restrict__ Ws,
    const float* __restrict__ gWhf,
    const float* __restrict__ word, const float* __restrict__ ih,
    const float* __restrict__ icc, const int* __restrict__ mask)
{
    if (blockIdx.x < PREP_BLOCKS) {
        size_t idx = (size_t)blockIdx.x*256 + threadIdx.x;
        if (idx < (size_t)CN*KXT) {
            int c = (int)(idx / KXT), j = (int)(idx % KXT);
            int g = c & 7, k = c >> 3;
            float v;
            if (j < 512)        v = Wx[((size_t)((g<<9)  + j       ))*512 + k];
            else if (j < 1536)  v = Wh[((size_t)((g<<10) + (j-512) ))*512 + k];
            else if (j < 2048)  v = Ws[((size_t)((g<<9)  + (j-1536)))*512 + k];
            else                v = Wi[((size_t)((g<<9)  + (j-2048)))*512 + k];
            g_WH[idx] = __float2half_rn(v);
        } else {
            int r = (int)(idx - (size_t)CN*KXT);     // < 512*512
            int kcol = r >> 9, j = r & 511;
            split2h(gWhf[j*512 + kcol], g_GH[r], g_GL[r]);
        }
    } else {
        size_t idx = (size_t)(blockIdx.x - PREP_BLOCKS)*256 + threadIdx.x;  // < Nn*512
        int n = (int)(idx >> 9), k = (int)(idx & 511);
        float m = (float)mask[n];
        float hv = ih[idx]*m;
        g_h[idx]  = hv;
        g_hA[idx] = __float2half_rn(hv);
        g_c[idx]  = icc[idx]*m;
        g_XA[(size_t)n*KXT + 2048 + k] = __float2half_rn(word[idx]*m);
    }
}

// mean(h)->dh[0] (y=0) and mean(c)->dc[0] (y=1), 4-way unrolled for MLP
__global__ void k_meanhc() {
    int b = blockIdx.x, k = threadIdx.x;
    const float* x = (blockIdx.y ? g_c : g_h) + ((size_t)(b<<9))*512 + k;
    float s0=0.f, s1=0.f, s2=0.f, s3=0.f;
    for (int t = 0; t < Ss; t += 4) {
        s0 += x[(size_t)t*512];       s1 += x[(size_t)(t+1)*512];
        s2 += x[(size_t)(t+2)*512];   s3 += x[(size_t)(t+3)*512];
    }
    float s = ((s0+s1)+(s2+s3)) * (1.f/512.f);
    int o = (b<<9) + k;
    if (blockIdx.y) g_dc[0][o] = s; else g_dh[0][o] = s;
}

// mean(h)->comb (layers >= 1)
__global__ void k_mean0() {
    int b = blockIdx.x, k = threadIdx.x;
    const float* x = g_h + ((size_t)(b<<9))*512 + k;
    float s0=0.f, s1=0.f, s2=0.f, s3=0.f;
    for (int t = 0; t < Ss; t += 4) {
        s0 += x[(size_t)t*512];       s1 += x[(size_t)(t+1)*512];
        s2 += x[(size_t)(t+2)*512];   s3 += x[(size_t)(t+3)*512];
    }
    g_comb[(b<<9) + k] = ((s0+s1)+(s2+s3)) * (1.f/512.f);
}

// small per-batch GEMMs: gd, go, gfx, zd[g]. layer0: comb == dh[0]
__global__ void k_small(const float* __restrict__ gW, const float* __restrict__ gb,
                        const float* __restrict__ Wd, int cur, int layer0) {
    int t = blockIdx.y;
    int idx = blockIdx.x*256 + threadIdx.x;   // 0..16383 = (b,k)
    int b = idx >> 9, k = idx & 511;
    const float* dh = g_dh[cur] + (b<<9);
    float s = 0.f;
    if (t <= 1) {
        const float* W1 = gW + (size_t)(t*2  )*262144;
        const float* W2 = gW + (size_t)(t*2+1)*262144;
        const float* cm = (layer0 ? g_dh[cur] : g_comb) + (b<<9);
        for (int j = 0; j < 512; j++)
            s = fmaf(dh[j], W1[j*512+k], fmaf(cm[j], W2[j*512+k], s));
        float v = sigm(s + gb[t*512 + k]);
        if (t == 0) g_gd[idx] = v; else g_go[idx] = v;
    } else if (t == 2) {
        const float* W = gW + (size_t)4*262144;   // gWxf
        for (int j = 0; j < 512; j++) s = fmaf(dh[j], W[j*512+k], s);
        g_gfx[idx] = s;
    } else {
        int g = t - 3;
        const float* W = Wd + (size_t)g*262144;
        for (int j = 0; j < 512; j++) s = fmaf(dh[j], W[j*512+k], s);
        g_zd[(b<<12) + (k<<3) + g] = s;
    }
}

// softmax over S+1 entries per (b,k) + new dummies
__global__ void k_soft(int cur) {
    int b = blockIdx.x, k = threadIdx.x;
    int bk = (b<<9) + k;
    float den = __expf(g_gd[bk] - 1.f);
    float num = den * g_dc[cur][bk];
    const float* gf = g_gf + (size_t)b*Ss*Hh + k;
    const float* cp = g_c  + (size_t)b*Ss*Hh + k;
    for (int s = 0; s < Ss; s++) {
        float w = __expf(gf[s*512] - 1.f);
        num = fmaf(w, cp[s*512], num);
        den += w;
    }
    float dcn = num/den;
    g_dc[cur^1][bk] = dcn;
    g_dh[cur^1][bk] = g_go[bk]*tanhf(dcn);
}

// X cols 0..2047 = [h | hb | ha | sw_h] fp16; also cb, ca, swc (fp32)
__global__ void k_build(const int* __restrict__ pos) {
    int n = blockIdx.x, k = threadIdx.x;
    int b = n >> 9, s = n & 511;
    size_t base = ((size_t)n << 9) + k;
    float hv = g_h[base];
    float hb = (s >= 1 ? g_h[base-512] : 0.f) + (s >= 2 ? g_h[base-1024] : 0.f);
    float ha = (s <= 510 ? g_h[base+512] : 0.f) + (s <= 509 ? g_h[base+1024] : 0.f);
    int p = pos[n];
    float sh = 0.f, sc = 0.f;
    if (p > 0) {
        size_t pb = ((size_t)((b<<9) + p - 1) << 9) + k;
        sh = g_h[pb]; sc = g_c[pb];
    }
    size_t xb = (size_t)n*KXT + k;
    g_XA[xb]        = __float2half_rn(hv);
    g_XA[xb + 512]  = __float2half_rn(hb);
    g_XA[xb + 1024] = __float2half_rn(ha);
    g_XA[xb + 1536] = __float2half_rn(sh);
    g_cb[base]  = (s >= 1 ? g_c[base-512] : 0.f) + (s >= 2 ? g_c[base-1024] : 0.f);
    g_ca[base]  = (s <= 510 ? g_c[base+512] : 0.f) + (s <= 509 ? g_c[base+1024] : 0.f);
    g_swc[base] = sc;
}

// ---------------- host ----------------
extern "C" void kernel_launch(void* const* d_in, const int* in_sizes, int n_in,
                              void* d_out, int out_size) {
    const float* word = (const float*)d_in[0];
    const float* ih   = (const float*)d_in[1];
    const float* icc  = (const float*)d_in[2];
    const float* Wx   = (const float*)d_in[3];
    const float* Wh   = (const float*)d_in[4];
    const float* Wi   = (const float*)d_in[5];
    const float* Wd   = (const float*)d_in[6];
    const float* Ws   = (const float*)d_in[7];
    const float* bias = (const float*)d_in[8];
    const float* gW   = (const float*)d_in[9];
    const float* gb   = (const float*)d_in[10];
    const int*   pos  = (const int*)d_in[11];
    const int*   mask = (const int*)d_in[12];
    float* out = (float*)d_out;

    cudaFuncSetAttribute(k_hgemm_big, cudaFuncAttributeMaxDynamicSharedMemorySize, SMEM_BYTES);
    cudaFuncSetAttribute(k_hgemm_gf,  cudaFuncAttributeMaxDynamicSharedMemorySize, SMEM_BYTES);
    cudaFuncSetAttribute(k_hgemm_zc,  cudaFuncAttributeMaxDynamicSharedMemorySize, SMEM_BYTES);

    k_prep_init<<<PREP_BLOCKS + INIT_BLOCKS, 256>>>(
        Wx, Wh, Wi, Ws, gW + (size_t)5*262144, word, ih, icc, mask);
    k_meanhc<<<dim3(Bb, 2), 512>>>();

    dim3 gbig(CN/BN, Nn/BM);   // (32, 64)
    dim3 ggf (Hh/BN, Nn/BM);   // (4, 64)
    k_hgemm_zc<<<gbig, 512, SMEM_BYTES>>>(bias);

    int cur = 0;
    for (int layer = 0; layer < NLAYERS; layer++) {
        if (layer > 0) k_mean0<<<Bb, 512>>>();
        k_small<<<dim3(64, 11), 256>>>(gW, gb, Wd, cur, layer == 0);
        k_hgemm_gf<<<ggf, 512, SMEM_BYTES>>>(gb + 1024, mask);
        k_soft <<<Bb, 512>>>(cur);
        k_build<<<Nn, 512>>>(pos);
        k_hgemm_big<<<gbig, 512, SMEM_BYTES>>>(mask, out, cur, layer == NLAYERS-1);
        cur ^= 1;
    }
}

// round 17
// speedup vs baseline: 1.1264x; 1.0528x over previous
#include <cuda_runtime.h>
#include <cuda_fp16.h>
#include <math.h>
#include <cstdint>

// Problem constants (fixed by reference setup_inputs)
#define Bb   32
#define Ss   512
#define Hh   512
#define Nn   (Bb*Ss)        // 16384 tokens
#define CN   4096           // 8 gates * H, interleaved c = k*8 + g
#define KXT  2560           // XA cols: [h | hb | ha | sw_h | emb]
#define KLY  2048           // per-layer GEMM K (emb hoisted into Zc)
#define NLAYERS 4

// HMMA GEMM: 256x128 tile, 512 threads (16 warps, 8x2), BK=64
#define BM 256
#define BN 128
#define BK 64
#define AROW 72                        // BK + 8 pad (halves); 144 bytes/row
#define A_BYTES  (BM*AROW*2)           // 36864
#define B_BYTES  (BN*AROW*2)           // 18432 per plane
#define SMEM_BYTES 221184              // = 4*(A+B) = 3*(A+2B); zs 256*132*4=135168 fits

// ---------------- device scratch ----------------
__device__ __half g_XA [(size_t)Nn*KXT];   // A single fp16 (cols 2048.. = emb)
__device__ __half g_WH [(size_t)CN*KXT];   // W fp16 [c][j] (cols 2048.. = Wi)
__device__ __half g_GH [(size_t)Hh*Hh];    // gWhf hi [c][j]
__device__ __half g_GL [(size_t)Hh*Hh];    // gWhf lo
__device__ __half g_hA [(size_t)Nn*Hh];    // h fp16 (gf GEMM A)
__device__ float g_Zc [(size_t)Nn*CN];     // emb@Wi + bias (layer-invariant), fp32
__device__ float g_h  [(size_t)Nn*Hh];
__device__ float g_c  [(size_t)Nn*Hh];
__device__ float g_cb [(size_t)Nn*Hh];
__device__ float g_ca [(size_t)Nn*Hh];
__device__ float g_swc[(size_t)Nn*Hh];
__device__ float g_gf [(size_t)Nn*Hh];
__device__ float g_zd [Bb*CN];
__device__ float g_dh [2][Bb*Hh];
__device__ float g_dc [2][Bb*Hh];
__device__ float g_comb[Bb*Hh];
__device__ float g_gd [Bb*Hh];
__device__ float g_go [Bb*Hh];
__device__ float g_gfx[Bb*Hh];

__device__ __forceinline__ float sigm(float x) { return 1.f/(1.f+__expf(-x)); }
__device__ __forceinline__ void split2h(float v, __half& hi, __half& lo) {
    hi = __float2half_rn(v);
    lo = __float2half_rn(v - __half2float(hi));
}

__device__ __forceinline__ uint32_t smem_u32(const void* p) {
    uint32_t a;
    asm("{ .reg .u64 t; cvta.to.shared.u64 t, %1; cvt.u32.u64 %0, t; }" : "=r"(a) : "l"(p));
    return a;
}
__device__ __forceinline__ void mma16816(float* c, const uint32_t* a, uint32_t b0, uint32_t b1) {
    asm volatile("mma.sync.aligned.m16n8k16.row.col.f32.f16.f16.f32 "
        "{%0,%1,%2,%3},{%4,%5,%6,%7},{%8,%9},{%0,%1,%2,%3};"
        : "+f"(c[0]), "+f"(c[1]), "+f"(c[2]), "+f"(c[3])
        : "r"(a[0]), "r"(a[1]), "r"(a[2]), "r"(a[3]), "r"(b0), "r"(b1));
}
#define LDSM_X4(r, addr) \
    asm volatile("ldmatrix.sync.aligned.m8n8.x4.shared.b16 {%0,%1,%2,%3},[%4];" \
        : "=r"((r)[0]), "=r"((r)[1]), "=r"((r)[2]), "=r"((r)[3]) : "r"(addr))
#define CP_ASYNC(dst, src) \
    asm volatile("cp.async.cg.shared.global [%0],[%1],16;" :: "r"(dst), "l"(src))
#define CP_COMMIT() asm volatile("cp.async.commit_group;")

// ---------------- HMMA mainloop: C[256x128], BK=64, templated B-split ----------------
template<int KCHUNKS, int NST, bool SPLITB>
__device__ __forceinline__ void hmma_mainloop(
    const __half* __restrict__ AAp, int lda,
    const __half* __restrict__ BHp, const __half* __restrict__ BLp, int ldb,
    int n0, int c0, char* smem, float acc[2][8][4])
{
    constexpr int STG = A_BYTES + (SPLITB ? 2 : 1)*B_BYTES;
    constexpr uint32_t BH_OFF = A_BYTES;
    constexpr uint32_t BL_OFF = A_BYTES + B_BYTES;
    const int tid = threadIdx.x, lane = tid & 31, wid = tid >> 5;
    const int wm = wid >> 1, wn = wid & 1;          // 8x2 warps, warp tile 32x64
    const uint32_t sb = smem_u32(smem);

    const uint32_t a_off0 = (uint32_t)(((wm*32 + (lane & 15))*AROW + (lane >> 4)*8) * 2);
    const uint32_t a_off1 = a_off0 + 16*AROW*2;
    const uint32_t b_off  = (uint32_t)(((wn*64 + ((lane >> 4) << 3) + (lane & 7))*AROW
                                        + ((lane >> 3) & 1)*8) * 2);

    auto issue = [&](int t) {
        const uint32_t base = sb + (t % NST)*STG;
        #pragma unroll
        for (int i = 0; i < 4; i++) {               // A: 2048 segs
            const int q = tid + i*512;
            const int row = q >> 3, seg = q & 7;
            const uint32_t off = (uint32_t)((row*AROW + seg*8)*2);
            CP_ASYNC(base + off, AAp + (size_t)(n0+row)*lda + t*BK + seg*8);
        }
        #pragma unroll
        for (int i = 0; i < 2; i++) {               // B: 1024 segs per plane
            const int q = tid + i*512;
            const int row = q >> 3, seg = q & 7;
            const uint32_t off = (uint32_t)((row*AROW + seg*8)*2);
            const size_t gsrcB = (size_t)(c0+row)*ldb + t*BK + seg*8;
            CP_ASYNC(base + BH_OFF + off, BHp + gsrcB);
            if (SPLITB) CP_ASYNC(base + BL_OFF + off, BLp + gsrcB);
        }
        CP_COMMIT();
    };

    #pragma unroll
    for (int i = 0; i < NST-1; i++) issue(i);
    #pragma unroll 1
    for (int t = 0; t < KCHUNKS; t++) {
        if (NST >= 4 && t + 3 <= KCHUNKS) asm volatile("cp.async.wait_group 2;");
        else if (t + 2 <= KCHUNKS)        asm volatile("cp.async.wait_group 1;");
        else                              asm volatile("cp.async.wait_group 0;");
        __syncthreads();
        if (t + NST - 1 < KCHUNKS) issue(t + NST - 1);   // stage (t-1)%NST: safe post-barrier
        const uint32_t base = sb + (t % NST)*STG;
        #pragma unroll
        for (int ks = 0; ks < 4; ks++) {
            const uint32_t kb = (uint32_t)(ks*32);  // 16 halves per k-step
            uint32_t Ahf[2][4];
            LDSM_X4(Ahf[0], base + a_off0 + kb);
            LDSM_X4(Ahf[1], base + a_off1 + kb);
            #pragma unroll
            for (int bp = 0; bp < 4; bp++) {
                uint32_t Bhf[4];
                LDSM_X4(Bhf, base + BH_OFF + b_off + bp*16*AROW*2 + kb);
                #pragma unroll
                for (int am = 0; am < 2; am++) {
                    mma16816(acc[am][2*bp],   Ahf[am], Bhf[0], Bhf[1]);
                    mma16816(acc[am][2*bp+1], Ahf[am], Bhf[2], Bhf[3]);
                }
                if (SPLITB) {
                    uint32_t Blf[4];
                    LDSM_X4(Blf, base + BL_OFF + b_off + bp*16*AROW*2 + kb);
                    #pragma unroll
                    for (int am = 0; am < 2; am++) {
                        mma16816(acc[am][2*bp],   Ahf[am], Blf[0], Blf[1]);
                        mma16816(acc[am][2*bp+1], Ahf[am], Blf[2], Blf[3]);
                    }
                }
            }
        }
    }
}

// ---------------- one-time Zc GEMM: Zc = emb @ Wi + bias (K=512) ----------------
__global__ void __launch_bounds__(512) k_hgemm_zc(const float* __restrict__ bias) {
    extern __shared__ char smem[];
    const int n0 = blockIdx.y*BM, c0 = blockIdx.x*BN;
    float acc[2][8][4] = {};
    hmma_mainloop<512/BK, 4, false>(g_XA + 2048, KXT, g_WH + 2048, nullptr, KXT,
                                    n0, c0, smem, acc);
    const int lane = threadIdx.x & 31, wid = threadIdx.x >> 5;
    const int wm = wid >> 1, wn = wid & 1;
    const int g = lane >> 2, tg2 = (lane & 3)*2;
    #pragma unroll
    for (int am = 0; am < 2; am++) {
        #pragma unroll
        for (int half = 0; half < 2; half++) {
            const int n = n0 + wm*32 + am*16 + g + half*8;
            #pragma unroll
            for (int na = 0; na < 8; na++) {
                const int cc = c0 + wn*64 + na*8 + tg2;
                float2 r;
                r.x = acc[am][na][half*2+0] + bias[(cc & 7)*512 + (cc >> 3)];
                r.y = acc[am][na][half*2+1] + bias[((cc+1) & 7)*512 + ((cc+1) >> 3)];
                *(float2*)&g_Zc[(size_t)n*CN + cc] = r;
            }
        }
    }
}

// ---------------- big GEMM (K=2048) + fused SLSTM epilogue ----------------
__global__ void __launch_bounds__(512) k_hgemm_big(
    const int* __restrict__ mask, float* __restrict__ out, int cur, int last)
{
    extern __shared__ char smem[];
    const int n0 = blockIdx.y*BM, c0 = blockIdx.x*BN;
    float acc[2][8][4] = {};
    hmma_mainloop<KLY/BK, 4, false>(g_XA, KXT, g_WH, nullptr, KXT, n0, c0, smem, acc);

    // stage z to smem (row stride 132 floats, 256 rows)
    float* zs = (float*)smem;
    const int lane = threadIdx.x & 31, wid = threadIdx.x >> 5;
    const int wm = wid >> 1, wn = wid & 1;
    const int g = lane >> 2, tg2 = (lane & 3)*2;
    __syncthreads();
    #pragma unroll
    for (int am = 0; am < 2; am++) {
        const int ra = wm*32 + am*16 + g;
        #pragma unroll
        for (int na = 0; na < 8; na++) {
            const int col = wn*64 + na*8 + tg2;
            *(float2*)&zs[ra*132 + col]     = *(float2*)&acc[am][na][0];
            *(float2*)&zs[(ra+8)*132 + col] = *(float2*)&acc[am][na][2];
        }
    }
    __syncthreads();

    // per-unit epilogue: 16 units x 256 rows in this tile
    const int u = threadIdx.x & 15, rgrp = threadIdx.x >> 4;   // 32 rgrps x 8 rows
    const int kout = (c0 >> 3) + u;
    const float* dc_old = g_dc[cur];
    float* hout = last ? out : g_h;

    #pragma unroll 1
    for (int i = 0; i < 8; i++) {
        const int n = n0 + rgrp*8 + i;
        const int b = n >> 9;
        const float m = (float)mask[n];
        float z[8];
        *(float4*)&z[0] = *(float4*)&zs[(rgrp*8+i)*132 + u*8];
        *(float4*)&z[4] = *(float4*)&zs[(rgrp*8+i)*132 + u*8 + 4];
        const float* zc = g_Zc + (size_t)n*CN + (kout<<3);
        float4 zc0 = *(const float4*)zc;
        float4 zc1 = *(const float4*)(zc + 4);
        z[0] += zc0.x; z[1] += zc0.y; z[2] += zc0.z; z[3] += zc0.w;
        z[4] += zc1.x; z[5] += zc1.y; z[6] += zc1.z; z[7] += zc1.w;
        #pragma unroll
        for (int gg = 0; gg < 8; gg++)
            z[gg] += g_zd[(b<<12)+(kout<<3)+gg];
        float e[6], ssum = 0.f;
        #pragma unroll
        for (int j = 0; j < 6; j++) { e[j] = __expf(sigm(z[j])); ssum += e[j]; }
        const float inv = 1.f/ssum;
        const float o = sigm(z[6]);
        const float u_t = tanhf(z[7]);
        const size_t idx = ((size_t)n << 9) + kout;
        float cn = (e[0]*g_cb[idx] + e[1]*g_ca[idx] + e[2]*g_c[idx]
                  + e[3]*dc_old[(b<<9)+kout] + e[4]*g_swc[idx] + e[5]*u_t) * inv;
        cn *= m;
        const float hv = o * tanhf(cn) * m;
        hout[idx] = hv;
        g_c[idx]  = cn;
        g_hA[idx] = __float2half_rn(hv);
    }
}

// ---------------- gf GEMM: gf = sigmoid(h @ gWhf + gfx + gbf) + mask_score ----------------
__global__ void __launch_bounds__(512) k_hgemm_gf(
    const float* __restrict__ gbf, const int* __restrict__ mask)
{
    extern __shared__ char smem[];
    const int n0 = blockIdx.y*BM, c0 = blockIdx.x*BN;
    float acc[2][8][4] = {};
    hmma_mainloop<Hh/BK, 3, true>(g_hA, Hh, g_GH, g_GL, Hh, n0, c0, smem, acc);

    const int lane = threadIdx.x & 31, wid = threadIdx.x >> 5;
    const int wm = wid >> 1, wn = wid & 1;
    const int g = lane >> 2, tg2 = (lane & 3)*2;
    #pragma unroll
    for (int am = 0; am < 2; am++) {
        #pragma unroll
        for (int half = 0; half < 2; half++) {
            const int n = n0 + wm*32 + am*16 + g + half*8;
            const int b = n >> 9;
            const float ms = mask[n] ? 0.f : -1e25f;
            #pragma unroll
            for (int na = 0; na < 8; na++) {
                const int cc = c0 + wn*64 + na*8 + tg2;
                float2 r;
                r.x = sigm(acc[am][na][half*2+0] + g_gfx[(b<<9)+cc]   + gbf[cc])   + ms;
                r.y = sigm(acc[am][na][half*2+1] + g_gfx[(b<<9)+cc+1] + gbf[cc+1]) + ms;
                *(float2*)&g_gf[((size_t)n<<9) + cc] = r;
            }
        }
    }
}

// ---------------- one-time prep (weights) + init (inputs), merged ----------------
#define PREP_ELEMS ((size_t)CN*KXT + (size_t)Hh*Hh)
#define PREP_BLOCKS ((int)(PREP_ELEMS/256))          // 41984
#define INIT_BLOCKS ((Nn*Hh)/256)                    // 32768
__global__ void k_prep_init(
    const float* __restrict__ Wx, const float* __restrict__ Wh,
    const float* __restrict__ Wi, const float* __restrict__ Ws,
    const float* __restrict__ gWhf,
    const float* __restrict__ word, const float* __restrict__ ih,
    const float* __restrict__ icc, const int* __restrict__ mask)
{
    if (blockIdx.x < PREP_BLOCKS) {
        size_t idx = (size_t)blockIdx.x*256 + threadIdx.x;
        if (idx < (size_t)CN*KXT) {
            int c = (int)(idx / KXT), j = (int)(idx % KXT);
            int g = c & 7, k = c >> 3;
            float v;
            if (j < 512)        v = Wx[((size_t)((g<<9)  + j       ))*512 + k];
            else if (j < 1536)  v = Wh[((size_t)((g<<10) + (j-512) ))*512 + k];
            else if (j < 2048)  v = Ws[((size_t)((g<<9)  + (j-1536)))*512 + k];
            else                v = Wi[((size_t)((g<<9)  + (j-2048)))*512 + k];
            g_WH[idx] = __float2half_rn(v);
        } else {
            int r = (int)(idx - (size_t)CN*KXT);     // < 512*512
            int kcol = r >> 9, j = r & 511;
            split2h(gWhf[j*512 + kcol], g_GH[r], g_GL[r]);
        }
    } else {
        size_t idx = (size_t)(blockIdx.x - PREP_BLOCKS)*256 + threadIdx.x;  // < Nn*512
        int n = (int)(idx >> 9), k = (int)(idx & 511);
        float m = (float)mask[n];
        float hv = ih[idx]*m;
        g_h[idx]  = hv;
        g_hA[idx] = __float2half_rn(hv);
        g_c[idx]  = icc[idx]*m;
        g_XA[(size_t)n*KXT + 2048 + k] = __float2half_rn(word[idx]*m);
    }
}

// mean(h)->dh[0] (y=0) and mean(c)->dc[0] (y=1), 8-way unrolled for MLP
__global__ void k_meanhc() {
    int b = blockIdx.x, k = threadIdx.x;
    const float* x = (blockIdx.y ? g_c : g_h) + ((size_t)(b<<9))*512 + k;
    float s0=0.f, s1=0.f, s2=0.f, s3=0.f, s4=0.f, s5=0.f, s6=0.f, s7=0.f;
    for (int t = 0; t < Ss; t += 8) {
        s0 += x[(size_t)t*512];       s1 += x[(size_t)(t+1)*512];
        s2 += x[(size_t)(t+2)*512];   s3 += x[(size_t)(t+3)*512];
        s4 += x[(size_t)(t+4)*512];   s5 += x[(size_t)(t+5)*512];
        s6 += x[(size_t)(t+6)*512];   s7 += x[(size_t)(t+7)*512];
    }
    float s = (((s0+s1)+(s2+s3)) + ((s4+s5)+(s6+s7))) * (1.f/512.f);
    int o = (b<<9) + k;
    if (blockIdx.y) g_dc[0][o] = s; else g_dh[0][o] = s;
}

// mean(h)->comb (layers >= 1), 8-way unrolled
__global__ void k_mean0() {
    int b = blockIdx.x, k = threadIdx.x;
    const float* x = g_h + ((size_t)(b<<9))*512 + k;
    float s0=0.f, s1=0.f, s2=0.f, s3=0.f, s4=0.f, s5=0.f, s6=0.f, s7=0.f;
    for (int t = 0; t < Ss; t += 8) {
        s0 += x[(size_t)t*512];       s1 += x[(size_t)(t+1)*512];
        s2 += x[(size_t)(t+2)*512];   s3 += x[(size_t)(t+3)*512];
        s4 += x[(size_t)(t+4)*512];   s5 += x[(size_t)(t+5)*512];
        s6 += x[(size_t)(t+6)*512];   s7 += x[(size_t)(t+7)*512];
    }
    g_comb[(b<<9) + k] = (((s0+s1)+(s2+s3)) + ((s4+s5)+(s6+s7))) * (1.f/512.f);
}

// small per-batch GEMMs: gd, go, gfx, zd[g]. layer0: comb == dh[0].
// 4-way unrolled accumulators (serial FMA chain was the R16 bottleneck: 187us/launch)
__global__ void k_small(const float* __restrict__ gW, const float* __restrict__ gb,
                        const float* __restrict__ Wd, int cur, int layer0) {
    int t = blockIdx.y;
    int idx = blockIdx.x*256 + threadIdx.x;   // 0..16383 = (b,k)
    int b = idx >> 9, k = idx & 511;
    const float* dh = g_dh[cur] + (b<<9);
    if (t <= 1) {
        const float* W1 = gW + (size_t)(t*2  )*262144;
        const float* W2 = gW + (size_t)(t*2+1)*262144;
        const float* cm = (layer0 ? g_dh[cur] : g_comb) + (b<<9);
        float s0=0.f, s1=0.f, s2=0.f, s3=0.f;
        #pragma unroll 4
        for (int j = 0; j < 512; j += 4) {
            s0 = fmaf(dh[j  ], W1[(j  )*512+k], fmaf(cm[j  ], W2[(j  )*512+k], s0));
            s1 = fmaf(dh[j+1], W1[(j+1)*512+k], fmaf(cm[j+1], W2[(j+1)*512+k], s1));
            s2 = fmaf(dh[j+2], W1[(j+2)*512+k], fmaf(cm[j+2], W2[(j+2)*512+k], s2));
            s3 = fmaf(dh[j+3], W1[(j+3)*512+k], fmaf(cm[j+3], W2[(j+3)*512+k], s3));
        }
        float v = sigm(((s0+s1)+(s2+s3)) + gb[t*512 + k]);
        if (t == 0) g_gd[idx] = v; else g_go[idx] = v;
    } else {
        const float* W = (t == 2) ? (gW + (size_t)4*262144)
                                  : (Wd + (size_t)(t-3)*262144);
        float s0=0.f, s1=0.f, s2=0.f, s3=0.f;
        #pragma unroll 4
        for (int j = 0; j < 512; j += 4) {
            s0 = fmaf(dh[j  ], W[(j  )*512+k], s0);
            s1 = fmaf(dh[j+1], W[(j+1)*512+k], s1);
            s2 = fmaf(dh[j+2], W[(j+2)*512+k], s2);
            s3 = fmaf(dh[j+3], W[(j+3)*512+k], s3);
        }
        float s = (s0+s1)+(s2+s3);
        if (t == 2) g_gfx[idx] = s;
        else        g_zd[(b<<12) + (k<<3) + (t-3)] = s;
    }
}

// softmax over S+1 entries per (b,k) + new dummies. 4-way unrolled chains.
__global__ void k_soft(int cur) {
    int b = blockIdx.x, k = threadIdx.x;
    int bk = (b<<9) + k;
    const float* gf = g_gf + (size_t)b*Ss*Hh + k;
    const float* cp = g_c  + (size_t)b*Ss*Hh + k;
    float n0=0.f, n1=0.f, n2=0.f, n3=0.f;
    float d0=0.f, d1=0.f, d2=0.f, d3=0.f;
    #pragma unroll 4
    for (int s = 0; s < 512; s += 4) {
        float w0 = __expf(gf[(s  )*512] - 1.f);
        float w1 = __expf(gf[(s+1)*512] - 1.f);
        float w2 = __expf(gf[(s+2)*512] - 1.f);
        float w3 = __expf(gf[(s+3)*512] - 1.f);
        n0 = fmaf(w0, cp[(s  )*512], n0);  d0 += w0;
        n1 = fmaf(w1, cp[(s+1)*512], n1);  d1 += w1;
        n2 = fmaf(w2, cp[(s+2)*512], n2);  d2 += w2;
        n3 = fmaf(w3, cp[(s+3)*512], n3);  d3 += w3;
    }
    float wd = __expf(g_gd[bk] - 1.f);
    float num = ((n0+n1)+(n2+n3)) + wd * g_dc[cur][bk];
    float den = ((d0+d1)+(d2+d3)) + wd;
    float dcn = num/den;
    g_dc[cur^1][bk] = dcn;
    g_dh[cur^1][bk] = g_go[bk]*tanhf(dcn);
}

// X cols 0..2047 = [h | hb | ha | sw_h] fp16; also cb, ca, swc (fp32)
__global__ void k_build(const int* __restrict__ pos) {
    int n = blockIdx.x, k = threadIdx.x;
    int b = n >> 9, s = n & 511;
    size_t base = ((size_t)n << 9) + k;
    float hv = g_h[base];
    float hb = (s >= 1 ? g_h[base-512] : 0.f) + (s >= 2 ? g_h[base-1024] : 0.f);
    float ha = (s <= 510 ? g_h[base+512] : 0.f) + (s <= 509 ? g_h[base+1024] : 0.f);
    int p = pos[n];
    float sh = 0.f, sc = 0.f;
    if (p > 0) {
        size_t pb = ((size_t)((b<<9) + p - 1) << 9) + k;
        sh = g_h[pb]; sc = g_c[pb];
    }
    size_t xb = (size_t)n*KXT + k;
    g_XA[xb]        = __float2half_rn(hv);
    g_XA[xb + 512]  = __float2half_rn(hb);
    g_XA[xb + 1024] = __float2half_rn(ha);
    g_XA[xb + 1536] = __float2half_rn(sh);
    g_cb[base]  = (s >= 1 ? g_c[base-512] : 0.f) + (s >= 2 ? g_c[base-1024] : 0.f);
    g_ca[base]  = (s <= 510 ? g_c[base+512] : 0.f) + (s <= 509 ? g_c[base+1024] : 0.f);
    g_swc[base] = sc;
}

// ---------------- host ----------------
extern "C" void kernel_launch(void* const* d_in, const int* in_sizes, int n_in,
                              void* d_out, int out_size) {
    const float* word = (const float*)d_in[0];
    const float* ih   = (const float*)d_in[1];
    const float* icc  = (const float*)d_in[2];
    const float* Wx   = (const float*)d_in[3];
    const float* Wh   = (const float*)d_in[4];
    const float* Wi   = (const float*)d_in[5];
    const float* Wd   = (const float*)d_in[6];
    const float* Ws   = (const float*)d_in[7];
    const float* bias = (const float*)d_in[8];
    const float* gW   = (const float*)d_in[9];
    const float* gb   = (const float*)d_in[10];
    const int*   pos  = (const int*)d_in[11];
    const int*   mask = (const int*)d_in[12];
    float* out = (float*)d_out;

    cudaFuncSetAttribute(k_hgemm_big, cudaFuncAttributeMaxDynamicSharedMemorySize, SMEM_BYTES);
    cudaFuncSetAttribute(k_hgemm_gf,  cudaFuncAttributeMaxDynamicSharedMemorySize, SMEM_BYTES);
    cudaFuncSetAttribute(k_hgemm_zc,  cudaFuncAttributeMaxDynamicSharedMemorySize, SMEM_BYTES);

    k_prep_init<<<PREP_BLOCKS + INIT_BLOCKS, 256>>>(
        Wx, Wh, Wi, Ws, gW + (size_t)5*262144, word, ih, icc, mask);
    k_meanhc<<<dim3(Bb, 2), 512>>>();

    dim3 gbig(CN/BN, Nn/BM);   // (32, 64)
    dim3 ggf (Hh/BN, Nn/BM);   // (4, 64)
    k_hgemm_zc<<<gbig, 512, SMEM_BYTES>>>(bias);

    int cur = 0;
    for (int layer = 0; layer < NLAYERS; layer++) {
        if (layer > 0) k_mean0<<<Bb, 512>>>();
        k_small<<<dim3(64, 11), 256>>>(gW, gb, Wd, cur, layer == 0);
        k_hgemm_gf<<<ggf, 512, SMEM_BYTES>>>(gb + 1024, mask);
        k_soft <<<Bb, 512>>>(cur);
        k_build<<<Nn, 512>>>(pos);
        k_hgemm_big<<<gbig, 512, SMEM_BYTES>>>(mask, out, cur, layer == NLAYERS-1);
        cur ^= 1;
    }
}